// round 17
// baseline (speedup 1.0000x reference)
#include <cuda_runtime.h>
#include <cuda_fp16.h>
#include <cstdint>
#include <cstddef>

// ---------------------------------------------------------------------------
// BinaryLinear: out[M,N] = x[M,K] @ sign(W)[N,K]^T + bias[N]
// M=8192, N=4096, K=4096 (fp32 in/out).
// Round 17: warp-specialized producer/consumer pipeline.
//   - 320 threads: 8 consumer warps (2Mx4N, 64x32 warp tile — unchanged)
//     + 2 producer warps owning ALL cp.async traffic
//   - 7-slab ring, per-slab full/empty mbarriers
//     full[s]: count 64, arrived via cp.async.mbarrier.arrive.noinc
//     empty[s]: count 256 (consumer threads)
//   - consumer mainloop is pure ldsm/mma/wait (R16 loop minus producer work)
// ---------------------------------------------------------------------------

#define BM 128
#define BN 128
#define BK 64
#define STAGES 7
#define NTHREADS 320
#define NCONS 256

#define SA_BYTES (BM * BK * 2)   // 16 KB
#define SB_BYTES (BN * BK * 2)   // 16 KB
#define SMEM_TILES (STAGES * (SA_BYTES + SB_BYTES))   // 224 KB
#define SMEM_TOTAL (SMEM_TILES + 128)                 // + barriers

// Scratch (device globals: no allocation allowed in kernel_launch)
__device__ __half g_xh[8192u * 4096u];   // x as fp16       [M,K]
__device__ __half g_wh[4096u * 4096u];   // sign(W) as fp16 [N,K]

// ---------------------- conversion kernels ---------------------------------

__global__ void cvt_x_kernel(const float4* __restrict__ x, int n4) {
    __half2* dst = reinterpret_cast<__half2*>(g_xh);
    int stride = gridDim.x * blockDim.x;
    for (int i = blockIdx.x * blockDim.x + threadIdx.x; i < n4; i += stride) {
        float4 v = x[i];
        dst[2 * i + 0] = __floats2half2_rn(v.x, v.y);
        dst[2 * i + 1] = __floats2half2_rn(v.z, v.w);
    }
}

__device__ __forceinline__ float fsign(float v) {
    return (v > 0.0f) ? 1.0f : ((v < 0.0f) ? -1.0f : 0.0f);
}

__global__ void cvt_w_kernel(const float4* __restrict__ w, int n4) {
    __half2* dst = reinterpret_cast<__half2*>(g_wh);
    int stride = gridDim.x * blockDim.x;
    for (int i = blockIdx.x * blockDim.x + threadIdx.x; i < n4; i += stride) {
        float4 v = w[i];
        dst[2 * i + 0] = __floats2half2_rn(fsign(v.x), fsign(v.y));
        dst[2 * i + 1] = __floats2half2_rn(fsign(v.z), fsign(v.w));
    }
}

// ---------------------- PTX helpers ----------------------------------------

__device__ __forceinline__ void cp_async16(uint32_t saddr, const void* gaddr) {
    asm volatile("cp.async.cg.shared.global [%0], [%1], 16;\n"
                 :: "r"(saddr), "l"(gaddr));
}

__device__ __forceinline__ void cp_async_mbar_arrive(uint32_t mbar) {
    asm volatile("cp.async.mbarrier.arrive.noinc.shared.b64 [%0];"
                 :: "r"(mbar) : "memory");
}

__device__ __forceinline__ void cp_async_wait_all() {
    asm volatile("cp.async.wait_all;" ::: "memory");
}

__device__ __forceinline__ void mbar_init(uint32_t addr, uint32_t count) {
    asm volatile("mbarrier.init.shared.b64 [%0], %1;"
                 :: "r"(addr), "r"(count) : "memory");
}

__device__ __forceinline__ void mbar_arrive(uint32_t addr) {
    asm volatile("mbarrier.arrive.shared.b64 _, [%0];"
                 :: "r"(addr) : "memory");
}

__device__ __forceinline__ void mbar_wait(uint32_t addr, uint32_t parity) {
    asm volatile(
        "{\n\t.reg .pred P;\n\t"
        "WAIT_%=:\n\t"
        "mbarrier.try_wait.parity.acquire.cta.shared::cta.b64 P, [%0], %1, 0x989680;\n\t"
        "@P bra DONE_%=;\n\t"
        "bra WAIT_%=;\n\t"
        "DONE_%=:\n\t}"
        :: "r"(addr), "r"(parity) : "memory");
}

__device__ __forceinline__ void ldsm4(uint32_t& r0, uint32_t& r1,
                                      uint32_t& r2, uint32_t& r3,
                                      uint32_t addr) {
    asm volatile("ldmatrix.sync.aligned.m8n8.x4.shared.b16 {%0,%1,%2,%3}, [%4];\n"
                 : "=r"(r0), "=r"(r1), "=r"(r2), "=r"(r3)
                 : "r"(addr));
}

__device__ __forceinline__ void mma16816(float* d, const uint32_t* a, const uint32_t* b) {
    asm volatile("mma.sync.aligned.m16n8k16.row.col.f32.f16.f16.f32 "
                 "{%0,%1,%2,%3}, {%4,%5,%6,%7}, {%8,%9}, {%0,%1,%2,%3};\n"
                 : "+f"(d[0]), "+f"(d[1]), "+f"(d[2]), "+f"(d[3])
                 : "r"(a[0]), "r"(a[1]), "r"(a[2]), "r"(a[3]),
                   "r"(b[0]), "r"(b[1]));
}

// load A+B fragments for one 16-wide k-step from stage s
__device__ __forceinline__ void load_frags(uint32_t a[4][4], uint32_t b[4][2],
                                           int ks, int s, int wm, int wn,
                                           int lane, uint32_t sA, uint32_t sB) {
#pragma unroll
    for (int mi = 0; mi < 4; mi++) {
        int row = wm * 64 + mi * 16 + (lane & 15);
        int chunk = 2 * ks + (lane >> 4);
        uint32_t addr = sA + s * SA_BYTES + row * 128 + ((chunk ^ (row & 7)) << 4);
        ldsm4(a[mi][0], a[mi][1], a[mi][2], a[mi][3], addr);
    }
#pragma unroll
    for (int nj = 0; nj < 2; nj++) {
        int row = wn * 32 + nj * 16 + (lane & 7) + ((lane >> 4) << 3);
        int chunk = 2 * ks + ((lane >> 3) & 1);
        uint32_t addr = sB + s * SB_BYTES + row * 128 + ((chunk ^ (row & 7)) << 4);
        ldsm4(b[2 * nj][0], b[2 * nj][1], b[2 * nj + 1][0], b[2 * nj + 1][1], addr);
    }
}

// ---------------------- GEMM kernel -----------------------------------------
// 320 threads: warps 0-7 consumers (2Mx4N, 64x32 tiles), warps 8-9 producers.

__global__ __launch_bounds__(NTHREADS, 1)
void bgemm_kernel(const float* __restrict__ bias, float* __restrict__ C,
                  int M, int N, int K) {
    extern __shared__ __align__(128) unsigned char smem_raw[];
    uint32_t sbase = (uint32_t)__cvta_generic_to_shared(smem_raw);
    uint32_t sA = sbase;
    uint32_t sB = sbase + STAGES * SA_BYTES;
    uint32_t barBase = sbase + SMEM_TILES;   // full[7] @ +0, empty[7] @ +64

    int tid = threadIdx.x;
    int lane = tid & 31;
    int wid = tid >> 5;
    int bm = blockIdx.y * BM;
    int bn = blockIdx.x * BN;
    int NK = K / BK;            // 64

    if (tid == 0) {
#pragma unroll
        for (int s = 0; s < STAGES; s++) {
            mbar_init(barBase + s * 8, 64);              // full[s]: producers
            mbar_init(barBase + 64 + s * 8, NCONS);      // empty[s]: consumers
        }
    }
    __syncthreads();   // one-time: barriers visible

    if (wid >= 8) {
        // ---------------- producer warps (64 threads) ----------------
        int ptid = tid - NCONS;      // 0..63
        int prow = ptid >> 3;        // 0..7
        int pchunk = ptid & 7;       // 0..7
        uint32_t swz = (uint32_t)((pchunk ^ prow) << 4);
        for (int q = 0; q < NK; q++) {
            int s = (unsigned)q % STAGES;
            unsigned rev = (unsigned)q / STAGES;
            if (rev > 0)
                mbar_wait(barBase + 64 + s * 8, (rev - 1) & 1);   // empty[s]
            const __half* Aq = g_xh + (size_t)(bm + prow) * K + (size_t)q * BK + pchunk * 8;
            uint32_t da = sA + s * SA_BYTES + prow * 128 + swz;
#pragma unroll
            for (int p = 0; p < 16; p++)
                cp_async16(da + p * 1024, Aq + (size_t)(p * 8) * K);
            const __half* Bq = g_wh + (size_t)(bn + prow) * K + (size_t)q * BK + pchunk * 8;
            uint32_t db = sB + s * SB_BYTES + prow * 128 + swz;
#pragma unroll
            for (int p = 0; p < 16; p++)
                cp_async16(db + p * 1024, Bq + (size_t)(p * 8) * K);
            cp_async_mbar_arrive(barBase + s * 8);                // full[s]
        }
        cp_async_wait_all();
        return;
    }

    // ---------------- consumer warps (256 threads) ----------------
    int wm = wid >> 2;          // 0..1
    int wn = wid & 3;           // 0..3

    float acc[4][4][4];
#pragma unroll
    for (int mi = 0; mi < 4; mi++)
#pragma unroll
        for (int ni = 0; ni < 4; ni++)
#pragma unroll
            for (int r = 0; r < 4; r++) acc[mi][ni][r] = 0.0f;

    uint32_t a[2][4][4], b[2][4][2];

    for (int j = 0; j < NK / 2; j++) {
        int kt0 = 2 * j;
        unsigned s0 = (unsigned)kt0 % STAGES;
        unsigned rev0 = (unsigned)kt0 / STAGES;
        unsigned s1 = (unsigned)(kt0 + 1) % STAGES;
        unsigned rev1 = (unsigned)(kt0 + 1) / STAGES;

        mbar_wait(barBase + s0 * 8, rev0 & 1);           // full[s0]
        load_frags(a[0], b[0], 0, s0, wm, wn, lane, sA, sB);

        // steps 0..2 on stage s0
#pragma unroll
        for (int step = 0; step < 3; step++) {
            int cur = step & 1;
            load_frags(a[cur ^ 1], b[cur ^ 1], step + 1, s0, wm, wn, lane, sA, sB);
#pragma unroll
            for (int mi = 0; mi < 4; mi++)
#pragma unroll
                for (int ni = 0; ni < 4; ni++)
                    mma16816(acc[mi][ni], a[cur][mi], b[cur][ni]);
        }

        mbar_wait(barBase + s1 * 8, rev1 & 1);           // full[s1]

        // step 3: last mma on s0; prefetch (s1, ks0)
        {
            int cur = 1;
            load_frags(a[0], b[0], 0, s1, wm, wn, lane, sA, sB);
#pragma unroll
            for (int mi = 0; mi < 4; mi++)
#pragma unroll
                for (int ni = 0; ni < 4; ni++)
                    mma16816(acc[mi][ni], a[cur][mi], b[cur][ni]);
        }
        mbar_arrive(barBase + 64 + s0 * 8);              // empty[s0]

        // steps 4..7 on stage s1
#pragma unroll
        for (int step = 4; step < 8; step++) {
            int cur = step & 1;
            if (step < 7)
                load_frags(a[cur ^ 1], b[cur ^ 1], (step + 1) & 3, s1,
                           wm, wn, lane, sA, sB);
#pragma unroll
            for (int mi = 0; mi < 4; mi++)
#pragma unroll
                for (int ni = 0; ni < 4; ni++)
                    mma16816(acc[mi][ni], a[cur][mi], b[cur][ni]);
        }
        mbar_arrive(barBase + 64 + s1 * 8);              // empty[s1]
    }

    // epilogue: add bias (hoisted), store fp32
    int crow = bm + wm * 64;
    int ccol = bn + wn * 32;
    float bh[4][2];
#pragma unroll
    for (int ni = 0; ni < 4; ni++) {
        int c = ccol + ni * 8 + (lane & 3) * 2;
        bh[ni][0] = bias[c];
        bh[ni][1] = bias[c + 1];
    }
#pragma unroll
    for (int mi = 0; mi < 4; mi++) {
        int r = crow + mi * 16 + (lane >> 2);
#pragma unroll
        for (int ni = 0; ni < 4; ni++) {
            int c = ccol + ni * 8 + (lane & 3) * 2;
            float2 v0 = make_float2(acc[mi][ni][0] + bh[ni][0], acc[mi][ni][1] + bh[ni][1]);
            float2 v1 = make_float2(acc[mi][ni][2] + bh[ni][0], acc[mi][ni][3] + bh[ni][1]);
            *reinterpret_cast<float2*>(C + (size_t)r * N + c) = v0;
            *reinterpret_cast<float2*>(C + (size_t)(r + 8) * N + c) = v1;
        }
    }
}

// ---------------------- launch ----------------------------------------------

extern "C" void kernel_launch(void* const* d_in, const int* in_sizes, int n_in,
                              void* d_out, int out_size) {
    const float* x = (const float*)d_in[0];     // [M,K] fp32
    const float* w = (const float*)d_in[1];     // [N,K] fp32
    const float* bias = (const float*)d_in[2];  // [N]   fp32
    float* out = (float*)d_out;                 // [M,N] fp32

    int N = in_sizes[2];
    int K = in_sizes[1] / N;
    int M = in_sizes[0] / K;

    cvt_x_kernel<<<4096, 256>>>((const float4*)x, (M * K) / 4);
    cvt_w_kernel<<<4096, 256>>>((const float4*)w, (N * K) / 4);

    // Persistent attribute; harmless outside capture, inherited by capture.
    cudaFuncSetAttribute(bgemm_kernel,
                         cudaFuncAttributeMaxDynamicSharedMemorySize, SMEM_TOTAL);

    dim3 grid(N / BN, M / BM);
    bgemm_kernel<<<grid, NTHREADS, SMEM_TOTAL>>>(bias, out, M, N, K);
}